// round 7
// baseline (speedup 1.0000x reference)
#include <cuda_runtime.h>
#include <cstdint>

#define CC   64
#define TR   128          // rows per block in pass1
#define MAXN 800000
#define MAXB 8

__device__ float g_scratch[(size_t)MAXN * CC];   // y' = x @ W1a^T
__device__ float g_wt[CC * CC];                  // W1a^T, pair-permuted (see k_prep)
__device__ float g_ssx[MAXB * CC];               // per-segment channel sums of x
__device__ float g_ssy[MAXB * CC];               // per-segment channel sums of y'
__device__ float g_ssq[CC];                      // global channel sums of y'^2
__device__ float g_a[CC];                        // folded BN scale
__device__ float g_d[MAXB * CC];                 // folded per-segment bias

// ---------------------------------------------------------------------------
// o may be int64 or int32 (jax x64 config). Positive cumulative offsets:
// if int64 (LE), high word of o[0] is 0.
// ---------------------------------------------------------------------------
__device__ __forceinline__ void load_bounds(const void* o, int B, int ob[MAXB]) {
    bool i64 = (((const int*)o)[1] == 0);
#pragma unroll
    for (int j = 0; j < MAXB; j++) {
        if (j < B) {
            long long v = i64 ? ((const long long*)o)[j] : (long long)((const int*)o)[j];
            ob[j] = (int)v;
        } else {
            ob[j] = 0x7fffffff;
        }
    }
}

__device__ __forceinline__ int seg_of(int row, const int ob[MAXB]) {
    int s = 0;
#pragma unroll
    for (int j = 0; j < MAXB; j++) s += (row >= ob[j]) ? 1 : 0;
    return s;
}

// ---------------------------------------------------------------------------
// prep: W1a^T with pair permutation (pair i -> slot (i>>2) | ((i&3)<<3),
// i.e. pair (4*cg + jp) lives at slot cg + 8*jp -> 8 distinct banks across cg,
// immediate-offset friendly for jp). Also zero accumulators.
// ---------------------------------------------------------------------------
__global__ void k_prep(const float* __restrict__ w1) {
    int t = blockIdx.x * blockDim.x + threadIdx.x;   // 0..4095
    int k = t >> 6, c = t & 63;
    int i = c >> 1;
    int p = (i >> 2) | ((i & 3) << 3);
    g_wt[k * 64 + 2 * p + (c & 1)] = w1[c * 2 * CC + k];
    if (t < MAXB * CC) { g_ssx[t] = 0.f; g_ssy[t] = 0.f; }
    if (t < CC) g_ssq[t] = 0.f;
}

// ---------------------------------------------------------------------------
// Pass 1: y' = x @ W1a^T fused with segsum(x), segsum(y'), sum(y'^2).
// 128 rows x 64 cols per block, 128 threads, thread tile 8 rows x 8 cols.
// xs: x scalar, row-major with k-XOR swizzle: x[r][k] at xs[r*64 + (k ^ s(r))],
//     s(r) = ((r>>3)&3)<<3.  GEMM LDS.32: 4 row-classes -> 4 distinct banks,
//     8-lane broadcast. Loader STS.128 covers full rows -> structural minimum.
// ws: pair-permuted W^T, reads are 8 distinct banks + 4-lane broadcast.
// ---------------------------------------------------------------------------
__global__ __launch_bounds__(128, 4) void k_pass1(const float* __restrict__ x,
                                                  const void* __restrict__ o,
                                                  int N, int B) {
    __shared__ float xs[TR * CC];    // 32KB
    __shared__ float ws[CC * CC];    // 16KB

    const int tid = threadIdx.x;
    const int w   = tid >> 5;
    const int l   = tid & 31;
    const int rowBase = blockIdx.x * TR;

    int s0, e0, s1c;
    {
        int ob[MAXB];
        load_bounds(o, B, ob);
        s0 = seg_of(rowBase, ob);
        if (s0 > B - 1) s0 = B - 1;
        e0 = ob[s0];
        s1c = min(s0 + 1, B - 1);
    }
    const bool hasB = (rowBase + TR > e0);

    // ---- ws copy (coalesced, conflict-free) ----
#pragma unroll
    for (int j = 0; j < 8; j++)
        ((float4*)ws)[tid + j * 128] = ((const float4*)g_wt)[tid + j * 128];

    // ---- x loader: swizzled scalar tile + per-element segment sums ----
    {
        const int lq = tid & 15;          // float4 index within row
        const int lr = tid >> 4;          // base row 0..7; rows lr + 8j
        float sx0x = 0.f, sx0y = 0.f, sx0z = 0.f, sx0w = 0.f;
        float sx1x = 0.f, sx1y = 0.f, sx1z = 0.f, sx1w = 0.f;
#pragma unroll
        for (int j = 0; j < 16; j++) {
            int r = lr + 8 * j;
            int row = rowBase + r;
            float4 v = make_float4(0.f, 0.f, 0.f, 0.f);
            if (row < N) v = ((const float4*)x)[(size_t)row * 16 + lq];
            int off = r * 64 + ((4 * lq) ^ (((r >> 3) & 3) << 3));
            *(float4*)&xs[off] = v;
            if (row >= e0) { sx1x += v.x; sx1y += v.y; sx1z += v.z; sx1w += v.w; }
            else           { sx0x += v.x; sx0y += v.y; sx0z += v.z; sx0w += v.w; }
        }
        // combine sibling lane (l^16 has same lq, other row set)
        sx0x += __shfl_xor_sync(0xffffffffu, sx0x, 16);
        sx0y += __shfl_xor_sync(0xffffffffu, sx0y, 16);
        sx0z += __shfl_xor_sync(0xffffffffu, sx0z, 16);
        sx0w += __shfl_xor_sync(0xffffffffu, sx0w, 16);
        sx1x += __shfl_xor_sync(0xffffffffu, sx1x, 16);
        sx1y += __shfl_xor_sync(0xffffffffu, sx1y, 16);
        sx1z += __shfl_xor_sync(0xffffffffu, sx1z, 16);
        sx1w += __shfl_xor_sync(0xffffffffu, sx1w, 16);
        if (l < 16) {
            float* p0 = &g_ssx[s0 * CC + 4 * lq];
            atomicAdd(p0 + 0, sx0x);
            atomicAdd(p0 + 1, sx0y);
            atomicAdd(p0 + 2, sx0z);
            atomicAdd(p0 + 3, sx0w);
            if (hasB) {
                float* p1 = &g_ssx[s1c * CC + 4 * lq];
                atomicAdd(p1 + 0, sx1x);
                atomicAdd(p1 + 1, sx1y);
                atomicAdd(p1 + 2, sx1z);
                atomicAdd(p1 + 3, sx1w);
            }
        }
    }
    __syncthreads();

    // ---- GEMM: thread = (rg, cg), rows 8rg..8rg+7, cols 8cg..8cg+7 ----
    const int cg = tid & 7;
    const int rg = tid >> 3;              // 0..15
    const int srg = (rg & 3) << 3;        // x swizzle for this thread's rows
    const float* xrow = xs + rg * 8 * 64;
    const float* wb = ws + 2 * cg;

    unsigned long long acc[8][4];
#pragma unroll
    for (int i = 0; i < 8; i++)
#pragma unroll
        for (int jp = 0; jp < 4; jp++) acc[i][jp] = 0ULL;

#pragma unroll 8
    for (int k = 0; k < CC; k++) {
        unsigned long long wp0 = *(const unsigned long long*)&wb[k * 64];
        unsigned long long wp1 = *(const unsigned long long*)&wb[k * 64 + 16];
        unsigned long long wp2 = *(const unsigned long long*)&wb[k * 64 + 32];
        unsigned long long wp3 = *(const unsigned long long*)&wb[k * 64 + 48];
        const int kx = k ^ srg;
#pragma unroll
        for (int i = 0; i < 8; i++) {
            float xv = xrow[i * 64 + kx];
            unsigned long long xp;
            asm("mov.b64 %0, {%1, %1};" : "=l"(xp) : "r"(__float_as_uint(xv)));
            asm("fma.rn.f32x2 %0, %1, %2, %0;" : "+l"(acc[i][0]) : "l"(xp), "l"(wp0));
            asm("fma.rn.f32x2 %0, %1, %2, %0;" : "+l"(acc[i][1]) : "l"(xp), "l"(wp1));
            asm("fma.rn.f32x2 %0, %1, %2, %0;" : "+l"(acc[i][2]) : "l"(xp), "l"(wp2));
            asm("fma.rn.f32x2 %0, %1, %2, %0;" : "+l"(acc[i][3]) : "l"(xp), "l"(wp3));
        }
    }

    // ---- epilogue: y' store (coalesced) + y' stats via global REDs ----
    float2 (*af)[4] = (float2 (*)[4])acc;

#pragma unroll
    for (int i = 0; i < 8; i++) {
        int row = rowBase + 8 * rg + i;
        if (row < N) {
            float4 u0 = make_float4(af[i][0].x, af[i][0].y, af[i][1].x, af[i][1].y);
            float4 u1 = make_float4(af[i][2].x, af[i][2].y, af[i][3].x, af[i][3].y);
            float4* p = (float4*)&g_scratch[(size_t)row * CC + 8 * cg];
            p[0] = u0;
            p[1] = u1;
        }
    }

    float ps[8], pq[8];
#pragma unroll
    for (int t = 0; t < 8; t++) {
        int jp = t >> 1;
        float s = 0.f, qq = 0.f;
#pragma unroll
        for (int i = 0; i < 8; i++) {
            float v = (t & 1) ? af[i][jp].y : af[i][jp].x;
            s += v; qq += v * v;
        }
        ps[t] = s; pq[t] = qq;
    }
    // reduce over the 4 rg-classes in the warp (same cg at l^8, l^16)
#pragma unroll
    for (int t = 0; t < 8; t++) {
        ps[t] += __shfl_xor_sync(0xffffffffu, ps[t], 8);
        ps[t] += __shfl_xor_sync(0xffffffffu, ps[t], 16);
        pq[t] += __shfl_xor_sync(0xffffffffu, pq[t], 8);
        pq[t] += __shfl_xor_sync(0xffffffffu, pq[t], 16);
    }
    // warp covers rows [rowBase+32w, rowBase+32w+32): uniform segment (bounds %32==0)
    int segw = ((rowBase + 32 * w) >= e0) ? s1c : s0;
    if (l < 8) {
        float* py = &g_ssy[segw * CC + 8 * l];
        float* pqg = &g_ssq[8 * l];
#pragma unroll
        for (int t = 0; t < 8; t++) {
            atomicAdd(py + t, ps[t]);
            atomicAdd(pqg + t, pq[t]);
        }
    }
}

// ---------------------------------------------------------------------------
// Tiny kernel: means -> h -> c -> analytic BN stats -> folded (a, d)
// ---------------------------------------------------------------------------
__global__ void k_mid(const void* __restrict__ o,
                      const float* __restrict__ w2, const float* __restrict__ b2,
                      const float* __restrict__ w1, const float* __restrict__ b1,
                      const float* __restrict__ gm, const float* __restrict__ bt,
                      int N, int B) {
    __shared__ float sm[MAXB][CC];
    __shared__ float sh[MAXB][CC];
    __shared__ float scn[MAXB];
    int oc = threadIdx.x;

    int ob[MAXB];
    load_bounds(o, B, ob);
    if (oc < MAXB) {
        int prev = (oc == 0) ? 0 : ob[oc - 1];
        scn[oc] = (oc < B) ? (float)(ob[oc] - prev) : 1.f;
    }
    __syncthreads();
    for (int b = 0; b < B; b++) sm[b][oc] = g_ssx[b * CC + oc] / scn[b];
    __syncthreads();
    for (int b = 0; b < B; b++) {
        float s = b2[oc];
        for (int ic = 0; ic < CC; ic++) s += sm[b][ic] * w2[oc * CC + ic];
        sh[b][oc] = fmaxf(s, 0.f);
    }
    __syncthreads();

    float cv[MAXB];
    float sumy = 0.f, ey2 = g_ssq[oc];
    for (int b = 0; b < B; b++) {
        float s = b1[oc];
        for (int ic = 0; ic < CC; ic++) s += sh[b][ic] * w1[oc * 2 * CC + CC + ic];
        cv[b] = s;
        float sy = g_ssy[b * CC + oc];
        sumy += sy + scn[b] * s;
        ey2 += 2.f * s * sy + scn[b] * s * s;
    }
    float invN = 1.f / (float)N;
    float mu = sumy * invN;
    float var = ey2 * invN - mu * mu;
    float a = gm[oc] * rsqrtf(var + 1e-5f);
    g_a[oc] = a;
    for (int b = 0; b < B; b++) g_d[b * CC + oc] = (cv[b] - mu) * a + bt[oc];
}

// ---------------------------------------------------------------------------
// Pass 2: out = relu(y' * a[ch] + d[seg][ch])   (pure streaming, float4)
// ---------------------------------------------------------------------------
__global__ __launch_bounds__(256) void k_pass2(const void* __restrict__ o,
                                               float* __restrict__ out,
                                               int N, int B) {
    __shared__ float sa[CC];
    __shared__ float sd[MAXB * CC];
    __shared__ int so[MAXB];
    int tid = threadIdx.x;
    if (tid < CC) sa[tid] = g_a[tid];
    for (int i2 = tid; i2 < MAXB * CC; i2 += 256) sd[i2] = g_d[i2];
    if (tid < MAXB) {
        int ob[MAXB];
        load_bounds(o, B, ob);
        so[tid] = ob[tid];
    }
    __syncthreads();

    int total4 = N * (CC / 4);
    for (int i = blockIdx.x * 256 + tid; i < total4; i += gridDim.x * 256) {
        int row = i >> 4;
        int c4 = (i & 15) << 2;
        int sg = 0;
#pragma unroll
        for (int j = 0; j < MAXB; j++) sg += (row >= so[j]) ? 1 : 0;
        if (sg >= B) sg = B - 1;

        float4 v = *(const float4*)&g_scratch[(size_t)i * 4];
        const float* dp = &sd[sg * CC + c4];
        v.x = fmaxf(fmaf(v.x, sa[c4 + 0], dp[0]), 0.f);
        v.y = fmaxf(fmaf(v.y, sa[c4 + 1], dp[1]), 0.f);
        v.z = fmaxf(fmaf(v.z, sa[c4 + 2], dp[2]), 0.f);
        v.w = fmaxf(fmaf(v.w, sa[c4 + 3], dp[3]), 0.f);
        *(float4*)&out[(size_t)i * 4] = v;
    }
}

// ---------------------------------------------------------------------------
extern "C" void kernel_launch(void* const* d_in, const int* in_sizes, int n_in,
                              void* d_out, int out_size) {
    const float* x  = (const float*)d_in[0];
    const void*  o  = d_in[1];
    const float* w2 = (const float*)d_in[2];
    const float* b2 = (const float*)d_in[3];
    const float* w1 = (const float*)d_in[4];
    const float* b1 = (const float*)d_in[5];
    const float* gm = (const float*)d_in[6];
    const float* bt = (const float*)d_in[7];
    float* out = (float*)d_out;

    int N = in_sizes[0] / CC;
    int B = in_sizes[1];
    if (B > MAXB) B = MAXB;
    if (N > MAXN) N = MAXN;

    k_prep<<<16, 256>>>(w1);
    int nb = (N + TR - 1) / TR;
    k_pass1<<<nb, 128>>>(x, o, N, B);
    k_mid<<<1, CC>>>(o, w2, b2, w1, b1, gm, bt, N, B);
    k_pass2<<<4096, 256>>>(o, out, N, B);
}